// round 1
// baseline (speedup 1.0000x reference)
#include <cuda_runtime.h>
#include <math.h>

#define NB 2
#define NN 50000
#define NE 640000
#define FD 128
#define NOUT 16
#define MR (NB*NN)   // 100000 rows

// ---------------- device scratch (allocation-free) ----------------
__device__ __align__(256) float g_norm[NE];
__device__ __align__(256) float g_dinv[NN];
__device__ __align__(256) float g_deg[NN];
__device__ __align__(256) float g_bufA[(size_t)MR*FD];   // xw / xw2
__device__ __align__(256) float g_bufH[(size_t)MR*FD];   // aggregated h
__device__ __align__(256) float g_stats[512];            // sum/sumsq for 2 layers
__device__ __align__(256) float g_W2p[FD*FD];            // a1 ⊙ W2
__device__ __align__(256) float g_cw2[FD];               // c1 @ W2
__device__ __align__(256) float g_Wcp[FD*NOUT];          // a2 ⊙ Wc
__device__ __align__(256) float g_bcp[NOUT];             // bc + c2 @ Wc

// ---------------- small prep kernels ----------------
__global__ void k_init() {
    int i = blockIdx.x*blockDim.x + threadIdx.x;
    if (i < NN) g_deg[i] = 1.0f;        // self-loop weight
    if (i < 512) g_stats[i] = 0.0f;
}

__global__ void k_deg(const int* __restrict__ ei, const float* __restrict__ ewp) {
    int e = blockIdx.x*blockDim.x + threadIdx.x;
    if (e >= NE) return;
    atomicAdd(&g_deg[ei[NE + e]], expf(ewp[e]));
}

__global__ void k_dinv() {
    int i = blockIdx.x*blockDim.x + threadIdx.x;
    if (i < NN) g_dinv[i] = rsqrtf(g_deg[i]);   // deg >= 1 always
}

__global__ void k_norm(const int* __restrict__ ei, const float* __restrict__ ewp) {
    int e = blockIdx.x*blockDim.x + threadIdx.x;
    if (e >= NE) return;
    g_norm[e] = g_dinv[ei[e]] * expf(ewp[e]) * g_dinv[ei[NE + e]];
}

// ---------------- fp32 SGEMM: C[MR,128] = A[MR,128] @ B[128,128] (+biasRow) ----------------
__global__ __launch_bounds__(256) void k_gemm(const float* __restrict__ A,
                                              const float* __restrict__ B,
                                              float* __restrict__ C,
                                              const float* __restrict__ biasRow) {
    __shared__ __align__(16) float As[8][132];  // [k][m], padded
    __shared__ __align__(16) float Bs[8][128];  // [k][n]
    const int t  = threadIdx.x;
    const int tr = t >> 4;       // 0..15 (row group)
    const int tc = t & 15;       // 0..15 (col group)
    const long rowBase = (long)blockIdx.x * 128;

    float bv[8];
    if (biasRow) {
        #pragma unroll
        for (int j = 0; j < 8; j++) bv[j] = biasRow[tc*8 + j];
    } else {
        #pragma unroll
        for (int j = 0; j < 8; j++) bv[j] = 0.f;
    }
    float acc[8][8];
    #pragma unroll
    for (int i = 0; i < 8; i++)
        #pragma unroll
        for (int j = 0; j < 8; j++) acc[i][j] = bv[j];

    const int arow = t >> 1;
    const int ac   = (t & 1) * 4;
    long arowg = rowBase + arow; if (arowg >= MR) arowg = MR - 1;
    const int brow = t >> 5;
    const int bcol = (t & 31) * 4;

    for (int kt = 0; kt < FD; kt += 8) {
        float4 av = *(const float4*)(A + arowg*FD + kt + ac);
        As[ac+0][arow] = av.x; As[ac+1][arow] = av.y;
        As[ac+2][arow] = av.z; As[ac+3][arow] = av.w;
        *(float4*)&Bs[brow][bcol] = *(const float4*)(B + (size_t)(kt + brow)*FD + bcol);
        __syncthreads();
        #pragma unroll
        for (int k = 0; k < 8; k++) {
            float4 a0 = *(const float4*)&As[k][tr*8];
            float4 a1 = *(const float4*)&As[k][tr*8 + 4];
            float4 b0 = *(const float4*)&Bs[k][tc*8];
            float4 b1 = *(const float4*)&Bs[k][tc*8 + 4];
            float ar[8] = {a0.x,a0.y,a0.z,a0.w,a1.x,a1.y,a1.z,a1.w};
            float br[8] = {b0.x,b0.y,b0.z,b0.w,b1.x,b1.y,b1.z,b1.w};
            #pragma unroll
            for (int i = 0; i < 8; i++)
                #pragma unroll
                for (int j = 0; j < 8; j++)
                    acc[i][j] = fmaf(ar[i], br[j], acc[i][j]);
        }
        __syncthreads();
    }
    #pragma unroll
    for (int i = 0; i < 8; i++) {
        long row = rowBase + tr*8 + i;
        if (row < MR) {
            float4 c0 = make_float4(acc[i][0], acc[i][1], acc[i][2], acc[i][3]);
            float4 c1 = make_float4(acc[i][4], acc[i][5], acc[i][6], acc[i][7]);
            *(float4*)(C + row*FD + tc*8)     = c0;
            *(float4*)(C + row*FD + tc*8 + 4) = c1;
        }
    }
}

// ---------------- init H with self-loop term + bias ----------------
__global__ void k_selfinit(const float* __restrict__ bias) {
    long idx = (long)blockIdx.x*blockDim.x + threadIdx.x;   // over MR*32 float4s
    if (idx >= (long)MR*32) return;
    long node = (idx >> 5) % NN;
    float d = g_dinv[node];
    float sn = d * d;
    float4 v = ((const float4*)g_bufA)[idx];
    float4 bvv = ((const float4*)bias)[idx & 31];
    float4 o = make_float4(fmaf(sn, v.x, bvv.x), fmaf(sn, v.y, bvv.y),
                           fmaf(sn, v.z, bvv.z), fmaf(sn, v.w, bvv.w));
    ((float4*)g_bufH)[idx] = o;
}

// ---------------- edge scatter: one warp per edge, vectorized f32 red ----------------
__global__ void k_scatter(const int* __restrict__ ei) {
    long gt = (long)blockIdx.x*blockDim.x + threadIdx.x;
    int e = (int)(gt >> 5);
    if (e >= NE) return;
    int lane = threadIdx.x & 31;
    int b = blockIdx.y;
    int r = ei[e], c = ei[NE + e];
    float nv = g_norm[e];
    const float4* src = (const float4*)(g_bufA + ((size_t)b*NN + r)*FD);
    float4 v = src[lane];
    float* dst = g_bufH + ((size_t)b*NN + c)*FD + lane*4;
    asm volatile("red.global.add.v4.f32 [%0], {%1,%2,%3,%4};"
                 :: "l"(dst), "f"(v.x*nv), "f"(v.y*nv), "f"(v.z*nv), "f"(v.w*nv)
                 : "memory");
}

// ---------------- fused ReLU (in place) + per-feature sum/sumsq ----------------
__global__ void k_relustats(int statoff) {
    int f = threadIdx.x;               // 128 threads = features
    long rb = (long)blockIdx.x * 64;
    float s = 0.f, s2 = 0.f;
    for (int i = 0; i < 64; i++) {
        long r = rb + i;
        if (r < MR) {
            float v = g_bufH[r*FD + f];
            v = fmaxf(v, 0.f);
            g_bufH[r*FD + f] = v;
            s += v; s2 += v*v;
        }
    }
    atomicAdd(&g_stats[statoff + f], s);
    atomicAdd(&g_stats[statoff + 128 + f], s2);
}

// ---------------- fold BN1 into W2: W2' = a1⊙W2, cw2 = c1@W2 ----------------
__global__ void k_fin1(const float* __restrict__ W2, const float* __restrict__ g1,
                       const float* __restrict__ be1) {
    __shared__ float a[FD], c[FD];
    int t = threadIdx.x;   // 128
    float inv = 1.0f / (float)MR;
    float mu  = g_stats[t] * inv;
    float var = g_stats[128 + t] * inv - mu*mu;
    float av  = g1[t] * rsqrtf(var + 1e-5f);
    a[t] = av; c[t] = be1[t] - mu*av;
    __syncthreads();
    float acc = 0.f;
    for (int f = 0; f < FD; f++) {
        float w = W2[f*FD + t];
        g_W2p[f*FD + t] = a[f]*w;
        acc = fmaf(c[f], w, acc);
    }
    g_cw2[t] = acc;
}

// ---------------- fold BN2 into Wc: Wc' = a2⊙Wc, bc' = bc + c2@Wc ----------------
__global__ void k_fin2(const float* __restrict__ Wc, const float* __restrict__ bc,
                       const float* __restrict__ g2, const float* __restrict__ be2) {
    __shared__ float a[FD], c[FD];
    int t = threadIdx.x;   // 128
    float inv = 1.0f / (float)MR;
    float mu  = g_stats[256 + t] * inv;
    float var = g_stats[384 + t] * inv - mu*mu;
    float av  = g2[t] * rsqrtf(var + 1e-5f);
    a[t] = av; c[t] = be2[t] - mu*av;
    __syncthreads();
    if (t < NOUT) {
        float acc = bc[t];
        for (int f = 0; f < FD; f++) {
            float w = Wc[f*NOUT + t];
            g_Wcp[f*NOUT + t] = a[f]*w;
            acc = fmaf(c[f], w, acc);
        }
        g_bcp[t] = acc;
    }
}

// ---------------- output head: out = H @ Wc' + bc' ----------------
__global__ void k_out(float* __restrict__ out) {
    __shared__ float Ws[FD*NOUT];
    __shared__ float Hs[8][FD];
    int t = threadIdx.x;   // 128
    #pragma unroll
    for (int i = 0; i < 16; i++) Ws[i*128 + t] = g_Wcp[i*128 + t];
    long rb = (long)blockIdx.x * 8;
    #pragma unroll
    for (int i = 0; i < 8; i++) {
        long r = rb + i;
        Hs[i][t] = (r < MR) ? g_bufH[r*FD + t] : 0.f;
    }
    __syncthreads();
    int rl = t >> 4, c = t & 15;
    float acc = g_bcp[c];
    #pragma unroll 8
    for (int f = 0; f < FD; f++) acc = fmaf(Hs[rl][f], Ws[f*NOUT + c], acc);
    long r = rb + rl;
    if (r < MR) out[r*NOUT + c] = acc;
}

// ---------------- launcher ----------------
extern "C" void kernel_launch(void* const* d_in, const int* in_sizes, int n_in,
                              void* d_out, int out_size) {
    const float* x   = (const float*)d_in[0];
    const int*   ei  = (const int*)  d_in[1];
    const float* ewp = (const float*)d_in[2];
    const float* W1  = (const float*)d_in[3];
    const float* b1  = (const float*)d_in[4];
    const float* W2  = (const float*)d_in[5];
    const float* b2  = (const float*)d_in[6];
    const float* g1  = (const float*)d_in[7];
    const float* be1 = (const float*)d_in[8];
    const float* g2  = (const float*)d_in[9];
    const float* be2 = (const float*)d_in[10];
    const float* Wc  = (const float*)d_in[11];
    const float* bc  = (const float*)d_in[12];
    float* out = (float*)d_out;

    float *bufA, *bufH, *W2p, *cw2;
    cudaGetSymbolAddress((void**)&bufA, g_bufA);
    cudaGetSymbolAddress((void**)&bufH, g_bufH);
    cudaGetSymbolAddress((void**)&W2p,  g_W2p);
    cudaGetSymbolAddress((void**)&cw2,  g_cw2);

    const int gemmBlocks = (MR + 127) / 128;          // 782
    const dim3 scGrid(NE/8, NB);                      // 80000 x 2, 8 edges/block

    k_init<<<(NN + 255)/256, 256>>>();
    k_deg<<<(NE + 255)/256, 256>>>(ei, ewp);
    k_dinv<<<(NN + 255)/256, 256>>>();
    k_norm<<<(NE + 255)/256, 256>>>(ei, ewp);

    // Layer 1
    k_gemm<<<gemmBlocks, 256>>>(x, W1, bufA, nullptr);
    k_selfinit<<<((long)MR*32 + 255)/256, 256>>>(b1);
    k_scatter<<<scGrid, 256>>>(ei);
    k_relustats<<<(MR + 63)/64, 128>>>(0);
    k_fin1<<<1, 128>>>(W2, g1, be1);

    // Layer 2 (BN1 folded into W2p/cw2)
    k_gemm<<<gemmBlocks, 256>>>(bufH, W2p, bufA, cw2);
    k_selfinit<<<((long)MR*32 + 255)/256, 256>>>(b2);
    k_scatter<<<scGrid, 256>>>(ei);
    k_relustats<<<(MR + 63)/64, 128>>>(256);
    k_fin2<<<1, 128>>>(Wc, bc, g2, be2);

    // Head (BN2 folded into Wcp/bcp)
    k_out<<<(MR + 7)/8, 128>>>(out);
}

// round 2
// speedup vs baseline: 1.3614x; 1.3614x over previous
#include <cuda_runtime.h>
#include <math.h>

#define NB 2
#define NN 50000
#define NE 640000
#define FD 128
#define NOUT 16
#define MR (NB*NN)   // 100000 rows

// ---------------- device scratch (allocation-free) ----------------
__device__ __align__(256) float g_dinv[NN];
__device__ __align__(256) float g_deg[NN];
__device__ __align__(256) int   g_cnt[NN];
__device__ __align__(256) int   g_cur[NN];
__device__ __align__(256) int   g_rowptr[NN + 1];
__device__ __align__(256) int   g_esrc[NE];     // src ids sorted by dst
__device__ __align__(256) float g_enorm[NE];    // norm sorted by dst
__device__ __align__(256) float g_bufA[(size_t)MR*FD];   // xw / xw2
__device__ __align__(256) float g_bufH[(size_t)MR*FD];   // aggregated h
__device__ __align__(256) float g_stats[512];            // sum/sumsq for 2 layers
__device__ __align__(256) float g_W2p[FD*FD];            // a1 ⊙ W2
__device__ __align__(256) float g_cw2[FD];               // c1 @ W2
__device__ __align__(256) float g_Wcp[FD*NOUT];          // a2 ⊙ Wc
__device__ __align__(256) float g_bcp[NOUT];             // bc + c2 @ Wc

// ---------------- prep: init, degree+histogram, dinv ----------------
__global__ void k_init() {
    int i = blockIdx.x*blockDim.x + threadIdx.x;
    if (i < NN) { g_deg[i] = 1.0f; g_cnt[i] = 0; }   // self-loop weight = 1
    if (i < 512) g_stats[i] = 0.0f;
}

__global__ void k_deghist(const int* __restrict__ ei, const float* __restrict__ ewp) {
    int e = blockIdx.x*blockDim.x + threadIdx.x;
    if (e >= NE) return;
    int dst = ei[NE + e];
    atomicAdd(&g_deg[dst], expf(ewp[e]));
    atomicAdd(&g_cnt[dst], 1);
}

__global__ void k_dinv() {
    int i = blockIdx.x*blockDim.x + threadIdx.x;
    if (i < NN) g_dinv[i] = rsqrtf(g_deg[i]);   // deg >= 1 always
}

// ---------------- 1-block exclusive scan over g_cnt -> g_rowptr, g_cur ----------------
__global__ __launch_bounds__(1024) void k_scan() {
    __shared__ int sh[1024];
    const int t = threadIdx.x;
    const int CH = (NN + 1023) / 1024;   // 49
    int base = t * CH;
    int s = 0;
    for (int i = 0; i < CH; i++) {
        int idx = base + i;
        if (idx < NN) s += g_cnt[idx];
    }
    sh[t] = s;
    __syncthreads();
    for (int off = 1; off < 1024; off <<= 1) {
        int v = (t >= off) ? sh[t - off] : 0;
        __syncthreads();
        sh[t] += v;
        __syncthreads();
    }
    int run = (t > 0) ? sh[t - 1] : 0;
    for (int i = 0; i < CH; i++) {
        int idx = base + i;
        if (idx < NN) {
            g_rowptr[idx] = run;
            g_cur[idx]    = run;
            run += g_cnt[idx];
        }
    }
    if (t == 1023) g_rowptr[NN] = sh[1023];
}

// ---------------- fill CSR buckets (src + norm, sorted by dst) ----------------
__global__ void k_fill(const int* __restrict__ ei, const float* __restrict__ ewp) {
    int e = blockIdx.x*blockDim.x + threadIdx.x;
    if (e >= NE) return;
    int src = ei[e], dst = ei[NE + e];
    int p = atomicAdd(&g_cur[dst], 1);
    g_esrc[p]  = src;
    g_enorm[p] = g_dinv[src] * expf(ewp[e]) * g_dinv[dst];
}

// ---------------- fp32 SGEMM: C[MR,128] = reluA?(A)[MR,128] @ B[128,128] (+biasRow) ----------------
__global__ __launch_bounds__(256) void k_gemm(const float* __restrict__ A,
                                              const float* __restrict__ B,
                                              float* __restrict__ C,
                                              const float* __restrict__ biasRow,
                                              int reluA) {
    __shared__ __align__(16) float As[8][132];  // [k][m], padded
    __shared__ __align__(16) float Bs[8][128];  // [k][n]
    const int t  = threadIdx.x;
    const int tr = t >> 4;       // 0..15 (row group)
    const int tc = t & 15;       // 0..15 (col group)
    const long rowBase = (long)blockIdx.x * 128;

    float bv[8];
    if (biasRow) {
        #pragma unroll
        for (int j = 0; j < 8; j++) bv[j] = biasRow[tc*8 + j];
    } else {
        #pragma unroll
        for (int j = 0; j < 8; j++) bv[j] = 0.f;
    }
    float acc[8][8];
    #pragma unroll
    for (int i = 0; i < 8; i++)
        #pragma unroll
        for (int j = 0; j < 8; j++) acc[i][j] = bv[j];

    const int arow = t >> 1;
    const int ac   = (t & 1) * 4;
    long arowg = rowBase + arow; if (arowg >= MR) arowg = MR - 1;
    const int brow = t >> 5;
    const int bcol = (t & 31) * 4;

    for (int kt = 0; kt < FD; kt += 8) {
        float4 av = *(const float4*)(A + arowg*FD + kt + ac);
        if (reluA) {
            av.x = fmaxf(av.x, 0.f); av.y = fmaxf(av.y, 0.f);
            av.z = fmaxf(av.z, 0.f); av.w = fmaxf(av.w, 0.f);
        }
        As[ac+0][arow] = av.x; As[ac+1][arow] = av.y;
        As[ac+2][arow] = av.z; As[ac+3][arow] = av.w;
        *(float4*)&Bs[brow][bcol] = *(const float4*)(B + (size_t)(kt + brow)*FD + bcol);
        __syncthreads();
        #pragma unroll
        for (int k = 0; k < 8; k++) {
            float4 a0 = *(const float4*)&As[k][tr*8];
            float4 a1 = *(const float4*)&As[k][tr*8 + 4];
            float4 b0 = *(const float4*)&Bs[k][tc*8];
            float4 b1 = *(const float4*)&Bs[k][tc*8 + 4];
            float ar[8] = {a0.x,a0.y,a0.z,a0.w,a1.x,a1.y,a1.z,a1.w};
            float br[8] = {b0.x,b0.y,b0.z,b0.w,b1.x,b1.y,b1.z,b1.w};
            #pragma unroll
            for (int i = 0; i < 8; i++)
                #pragma unroll
                for (int j = 0; j < 8; j++)
                    acc[i][j] = fmaf(ar[i], br[j], acc[i][j]);
        }
        __syncthreads();
    }
    #pragma unroll
    for (int i = 0; i < 8; i++) {
        long row = rowBase + tr*8 + i;
        if (row < MR) {
            float4 c0 = make_float4(acc[i][0], acc[i][1], acc[i][2], acc[i][3]);
            float4 c1 = make_float4(acc[i][4], acc[i][5], acc[i][6], acc[i][7]);
            *(float4*)(C + row*FD + tc*8)     = c0;
            *(float4*)(C + row*FD + tc*8 + 4) = c1;
        }
    }
}

// ---------------- CSR aggregation: one warp per node, single write ----------------
// H[b,n] = dinv[n]^2 * A[b,n] + bias + sum_{edges e: dst=n} norm[e] * A[b,src[e]]
__global__ __launch_bounds__(256) void k_agg(const float* __restrict__ A,
                                             float* __restrict__ H,
                                             const float* __restrict__ bias) {
    int warp = threadIdx.x >> 5;
    int lane = threadIdx.x & 31;
    int n = blockIdx.x * 8 + warp;
    if (n >= NN) return;
    int b = blockIdx.y;
    const float4* Ab = (const float4*)(A + (size_t)b*NN*FD);

    float d = g_dinv[n];
    float sn = d * d;
    float4 v  = Ab[(size_t)n*32 + lane];
    float4 bv = ((const float4*)bias)[lane];
    float4 acc;
    acc.x = fmaf(sn, v.x, bv.x);
    acc.y = fmaf(sn, v.y, bv.y);
    acc.z = fmaf(sn, v.z, bv.z);
    acc.w = fmaf(sn, v.w, bv.w);

    int j = g_rowptr[n];
    const int e = g_rowptr[n + 1];
    for (; j + 1 < e; j += 2) {
        int sA = g_esrc[j],   sB = g_esrc[j+1];
        float nA = g_enorm[j], nB = g_enorm[j+1];
        float4 vA = Ab[(size_t)sA*32 + lane];
        float4 vB = Ab[(size_t)sB*32 + lane];
        acc.x = fmaf(nA, vA.x, acc.x); acc.y = fmaf(nA, vA.y, acc.y);
        acc.z = fmaf(nA, vA.z, acc.z); acc.w = fmaf(nA, vA.w, acc.w);
        acc.x = fmaf(nB, vB.x, acc.x); acc.y = fmaf(nB, vB.y, acc.y);
        acc.z = fmaf(nB, vB.z, acc.z); acc.w = fmaf(nB, vB.w, acc.w);
    }
    if (j < e) {
        int sA = g_esrc[j];
        float nA = g_enorm[j];
        float4 vA = Ab[(size_t)sA*32 + lane];
        acc.x = fmaf(nA, vA.x, acc.x); acc.y = fmaf(nA, vA.y, acc.y);
        acc.z = fmaf(nA, vA.z, acc.z); acc.w = fmaf(nA, vA.w, acc.w);
    }
    ((float4*)(H + ((size_t)b*NN + n)*FD))[lane] = acc;
}

// ---------------- per-feature sum/sumsq of relu(H) (read-only) ----------------
__global__ void k_relustats(int statoff) {
    int f = threadIdx.x;               // 128 threads = features
    long rb = (long)blockIdx.x * 64;
    float s = 0.f, s2 = 0.f;
    for (int i = 0; i < 64; i++) {
        long r = rb + i;
        if (r < MR) {
            float v = fmaxf(g_bufH[r*FD + f], 0.f);
            s += v; s2 += v*v;
        }
    }
    atomicAdd(&g_stats[statoff + f], s);
    atomicAdd(&g_stats[statoff + 128 + f], s2);
}

// ---------------- fold BN1 into W2: W2' = a1⊙W2, cw2 = c1@W2 ----------------
__global__ void k_fin1(const float* __restrict__ W2, const float* __restrict__ g1,
                       const float* __restrict__ be1) {
    __shared__ float a[FD], c[FD];
    int t = threadIdx.x;   // 128
    float inv = 1.0f / (float)MR;
    float mu  = g_stats[t] * inv;
    float var = g_stats[128 + t] * inv - mu*mu;
    float av  = g1[t] * rsqrtf(var + 1e-5f);
    a[t] = av; c[t] = be1[t] - mu*av;
    __syncthreads();
    float acc = 0.f;
    for (int f = 0; f < FD; f++) {
        float w = W2[f*FD + t];
        g_W2p[f*FD + t] = a[f]*w;
        acc = fmaf(c[f], w, acc);
    }
    g_cw2[t] = acc;
}

// ---------------- fold BN2 into Wc: Wc' = a2⊙Wc, bc' = bc + c2@Wc ----------------
__global__ void k_fin2(const float* __restrict__ Wc, const float* __restrict__ bc,
                       const float* __restrict__ g2, const float* __restrict__ be2) {
    __shared__ float a[FD], c[FD];
    int t = threadIdx.x;   // 128
    float inv = 1.0f / (float)MR;
    float mu  = g_stats[256 + t] * inv;
    float var = g_stats[384 + t] * inv - mu*mu;
    float av  = g2[t] * rsqrtf(var + 1e-5f);
    a[t] = av; c[t] = be2[t] - mu*av;
    __syncthreads();
    if (t < NOUT) {
        float acc = bc[t];
        for (int f = 0; f < FD; f++) {
            float w = Wc[f*NOUT + t];
            g_Wcp[f*NOUT + t] = a[f]*w;
            acc = fmaf(c[f], w, acc);
        }
        g_bcp[t] = acc;
    }
}

// ---------------- output head: out = relu(H) @ Wc' + bc' ----------------
__global__ void k_out(float* __restrict__ out) {
    __shared__ float Ws[FD*NOUT];
    __shared__ float Hs[8][FD];
    int t = threadIdx.x;   // 128
    #pragma unroll
    for (int i = 0; i < 16; i++) Ws[i*128 + t] = g_Wcp[i*128 + t];
    long rb = (long)blockIdx.x * 8;
    #pragma unroll
    for (int i = 0; i < 8; i++) {
        long r = rb + i;
        Hs[i][t] = (r < MR) ? fmaxf(g_bufH[r*FD + t], 0.f) : 0.f;
    }
    __syncthreads();
    int rl = t >> 4, c = t & 15;
    float acc = g_bcp[c];
    #pragma unroll 8
    for (int f = 0; f < FD; f++) acc = fmaf(Hs[rl][f], Ws[f*NOUT + c], acc);
    long r = rb + rl;
    if (r < MR) out[r*NOUT + c] = acc;
}

// ---------------- launcher ----------------
extern "C" void kernel_launch(void* const* d_in, const int* in_sizes, int n_in,
                              void* d_out, int out_size) {
    const float* x   = (const float*)d_in[0];
    const int*   ei  = (const int*)  d_in[1];
    const float* ewp = (const float*)d_in[2];
    const float* W1  = (const float*)d_in[3];
    const float* b1  = (const float*)d_in[4];
    const float* W2  = (const float*)d_in[5];
    const float* b2  = (const float*)d_in[6];
    const float* g1  = (const float*)d_in[7];
    const float* be1 = (const float*)d_in[8];
    const float* g2  = (const float*)d_in[9];
    const float* be2 = (const float*)d_in[10];
    const float* Wc  = (const float*)d_in[11];
    const float* bc  = (const float*)d_in[12];
    float* out = (float*)d_out;

    float *bufA, *bufH, *W2p, *cw2;
    cudaGetSymbolAddress((void**)&bufA, g_bufA);
    cudaGetSymbolAddress((void**)&bufH, g_bufH);
    cudaGetSymbolAddress((void**)&W2p,  g_W2p);
    cudaGetSymbolAddress((void**)&cw2,  g_cw2);

    const int gemmBlocks = (MR + 127) / 128;          // 782
    const dim3 aggGrid((NN + 7) / 8, NB);             // 6250 x 2

    // prep + CSR build (shared by both layers/batches)
    k_init<<<(NN + 255)/256, 256>>>();
    k_deghist<<<(NE + 255)/256, 256>>>(ei, ewp);
    k_dinv<<<(NN + 255)/256, 256>>>();
    k_scan<<<1, 1024>>>();
    k_fill<<<(NE + 255)/256, 256>>>(ei, ewp);

    // Layer 1
    k_gemm<<<gemmBlocks, 256>>>(x, W1, bufA, nullptr, 0);
    k_agg<<<aggGrid, 256>>>(bufA, bufH, b1);
    k_relustats<<<(MR + 63)/64, 128>>>(0);
    k_fin1<<<1, 128>>>(W2, g1, be1);

    // Layer 2 (ReLU applied in GEMM A-load; BN1 folded into W2p/cw2)
    k_gemm<<<gemmBlocks, 256>>>(bufH, W2p, bufA, cw2, 1);
    k_agg<<<aggGrid, 256>>>(bufA, bufH, b2);
    k_relustats<<<(MR + 63)/64, 128>>>(256);
    k_fin2<<<1, 128>>>(Wc, bc, g2, be2);

    // Head (ReLU applied in load; BN2 folded into Wcp/bcp)
    k_out<<<(MR + 7)/8, 128>>>(out);
}

// round 3
// speedup vs baseline: 1.5578x; 1.1443x over previous
#include <cuda_runtime.h>
#include <math.h>

#define NB 2
#define NN 50000
#define NE 640000
#define FD 128
#define NOUT 16
#define MR (NB*NN)   // 100000 rows
#define SB 49        // scan blocks (49*1024 >= NN)

// ---------------- device scratch (allocation-free) ----------------
__device__ __align__(256) float g_dinv[NN];
__device__ __align__(256) float g_deg[NN];
__device__ __align__(256) int   g_cnt[NN];
__device__ __align__(256) int   g_cur[NN];
__device__ __align__(256) int   g_rowptr[NN + 1];
__device__ __align__(256) int   g_bsum[SB];
__device__ __align__(256) int   g_boff[SB];
__device__ __align__(256) int   g_esrc[NE];     // src ids sorted by dst
__device__ __align__(256) float g_enorm[NE];    // norm sorted by dst
__device__ __align__(256) float g_bufA[(size_t)MR*FD];   // xw / xw2
__device__ __align__(256) float g_bufH[(size_t)MR*FD];   // aggregated h
__device__ __align__(256) float g_stats[512];            // sum/sumsq for 2 layers
__device__ __align__(256) float g_W2p[FD*FD];            // a1 ⊙ W2
__device__ __align__(256) float g_cw2[FD];               // c1 @ W2
__device__ __align__(256) float g_Wcp[FD*NOUT];          // a2 ⊙ Wc
__device__ __align__(256) float g_bcp[NOUT];             // bc + c2 @ Wc

// ---------------- prep: init, degree+histogram, dinv ----------------
__global__ void k_init() {
    int i = blockIdx.x*blockDim.x + threadIdx.x;
    if (i < NN) { g_deg[i] = 1.0f; g_cnt[i] = 0; }   // self-loop weight = 1
    if (i < 512) g_stats[i] = 0.0f;
}

__global__ void k_deghist(const int* __restrict__ ei, const float* __restrict__ ewp) {
    int e = blockIdx.x*blockDim.x + threadIdx.x;
    if (e >= NE) return;
    int dst = ei[NE + e];
    atomicAdd(&g_deg[dst], expf(ewp[e]));
    atomicAdd(&g_cnt[dst], 1);
}

__global__ void k_dinv() {
    int i = blockIdx.x*blockDim.x + threadIdx.x;
    if (i < NN) g_dinv[i] = rsqrtf(g_deg[i]);   // deg >= 1 always
}

// ---------------- parallel 3-phase exclusive scan over g_cnt ----------------
__global__ __launch_bounds__(1024) void k_scan1() {
    __shared__ int sh[1024];
    const int t = threadIdx.x;
    const int i = blockIdx.x * 1024 + t;
    int v = (i < NN) ? g_cnt[i] : 0;
    sh[t] = v;
    __syncthreads();
    #pragma unroll
    for (int off = 1; off < 1024; off <<= 1) {
        int x = (t >= off) ? sh[t - off] : 0;
        __syncthreads();
        sh[t] += x;
        __syncthreads();
    }
    if (i < NN) g_rowptr[i] = sh[t] - v;        // local exclusive prefix
    if (t == 1023) g_bsum[blockIdx.x] = sh[1023];
}

__global__ void k_scan2() {
    __shared__ int s[SB];
    int t = threadIdx.x;   // 64 threads
    if (t < SB) s[t] = g_bsum[t];
    __syncthreads();
    if (t == 0) {
        int run = 0;
        for (int i = 0; i < SB; i++) { int v = s[i]; s[i] = run; run += v; }
    }
    __syncthreads();
    if (t < SB) g_boff[t] = s[t];
}

__global__ __launch_bounds__(1024) void k_scan3() {
    const int i = blockIdx.x * 1024 + threadIdx.x;
    if (i < NN) {
        int v = g_rowptr[i] + g_boff[blockIdx.x];
        g_rowptr[i] = v;
        g_cur[i]    = v;
    }
    if (i == 0) g_rowptr[NN] = NE;
}

// ---------------- fill CSR buckets (src + norm, sorted by dst) ----------------
__global__ void k_fill(const int* __restrict__ ei, const float* __restrict__ ewp) {
    int e = blockIdx.x*blockDim.x + threadIdx.x;
    if (e >= NE) return;
    int src = ei[e], dst = ei[NE + e];
    int p = atomicAdd(&g_cur[dst], 1);
    g_esrc[p]  = src;
    g_enorm[p] = g_dinv[src] * expf(ewp[e]) * g_dinv[dst];
}

// ---------------- fp32 SGEMM: C[MR,128] = reluA?(A)[MR,128] @ B[128,128] (+biasRow) ----------------
__global__ __launch_bounds__(256) void k_gemm(const float* __restrict__ A,
                                              const float* __restrict__ B,
                                              float* __restrict__ C,
                                              const float* __restrict__ biasRow,
                                              int reluA) {
    __shared__ __align__(16) float As[8][132];  // [k][m], padded
    __shared__ __align__(16) float Bs[8][128];  // [k][n]
    const int t  = threadIdx.x;
    const int tr = t >> 4;       // 0..15 (row group)
    const int tc = t & 15;       // 0..15 (col group)
    const long rowBase = (long)blockIdx.x * 128;

    float bv[8];
    if (biasRow) {
        #pragma unroll
        for (int j = 0; j < 8; j++) bv[j] = biasRow[tc*8 + j];
    } else {
        #pragma unroll
        for (int j = 0; j < 8; j++) bv[j] = 0.f;
    }
    float acc[8][8];
    #pragma unroll
    for (int i = 0; i < 8; i++)
        #pragma unroll
        for (int j = 0; j < 8; j++) acc[i][j] = bv[j];

    const int arow = t >> 1;
    const int ac   = (t & 1) * 4;
    long arowg = rowBase + arow; if (arowg >= MR) arowg = MR - 1;
    const int brow = t >> 5;
    const int bcol = (t & 31) * 4;

    for (int kt = 0; kt < FD; kt += 8) {
        float4 av = *(const float4*)(A + arowg*FD + kt + ac);
        if (reluA) {
            av.x = fmaxf(av.x, 0.f); av.y = fmaxf(av.y, 0.f);
            av.z = fmaxf(av.z, 0.f); av.w = fmaxf(av.w, 0.f);
        }
        As[ac+0][arow] = av.x; As[ac+1][arow] = av.y;
        As[ac+2][arow] = av.z; As[ac+3][arow] = av.w;
        *(float4*)&Bs[brow][bcol] = *(const float4*)(B + (size_t)(kt + brow)*FD + bcol);
        __syncthreads();
        #pragma unroll
        for (int k = 0; k < 8; k++) {
            float4 a0 = *(const float4*)&As[k][tr*8];
            float4 a1 = *(const float4*)&As[k][tr*8 + 4];
            float4 b0 = *(const float4*)&Bs[k][tc*8];
            float4 b1 = *(const float4*)&Bs[k][tc*8 + 4];
            float ar[8] = {a0.x,a0.y,a0.z,a0.w,a1.x,a1.y,a1.z,a1.w};
            float br[8] = {b0.x,b0.y,b0.z,b0.w,b1.x,b1.y,b1.z,b1.w};
            #pragma unroll
            for (int i = 0; i < 8; i++)
                #pragma unroll
                for (int j = 0; j < 8; j++)
                    acc[i][j] = fmaf(ar[i], br[j], acc[i][j]);
        }
        __syncthreads();
    }
    #pragma unroll
    for (int i = 0; i < 8; i++) {
        long row = rowBase + tr*8 + i;
        if (row < MR) {
            float4 c0 = make_float4(acc[i][0], acc[i][1], acc[i][2], acc[i][3]);
            float4 c1 = make_float4(acc[i][4], acc[i][5], acc[i][6], acc[i][7]);
            *(float4*)(C + row*FD + tc*8)     = c0;
            *(float4*)(C + row*FD + tc*8 + 4) = c1;
        }
    }
}

// ---------------- CSR aggregation: one warp per node, single write ----------------
// H[b,n] = dinv[n]^2 * A[b,n] + bias + sum_{edges e: dst=n} norm[e] * A[b,src[e]]
__global__ __launch_bounds__(256) void k_agg(const float* __restrict__ A,
                                             float* __restrict__ H,
                                             const float* __restrict__ bias) {
    int warp = threadIdx.x >> 5;
    int lane = threadIdx.x & 31;
    int n = blockIdx.x * 8 + warp;
    if (n >= NN) return;
    int b = blockIdx.y;
    const float4* Ab = (const float4*)(A + (size_t)b*NN*FD);

    float d = g_dinv[n];
    float sn = d * d;
    float4 v  = Ab[(size_t)n*32 + lane];
    float4 bv = ((const float4*)bias)[lane];
    float4 acc;
    acc.x = fmaf(sn, v.x, bv.x);
    acc.y = fmaf(sn, v.y, bv.y);
    acc.z = fmaf(sn, v.z, bv.z);
    acc.w = fmaf(sn, v.w, bv.w);

    int j = g_rowptr[n];
    const int e = g_rowptr[n + 1];
    for (; j + 1 < e; j += 2) {
        int sA = g_esrc[j],   sB = g_esrc[j+1];
        float nA = g_enorm[j], nB = g_enorm[j+1];
        float4 vA = Ab[(size_t)sA*32 + lane];
        float4 vB = Ab[(size_t)sB*32 + lane];
        acc.x = fmaf(nA, vA.x, acc.x); acc.y = fmaf(nA, vA.y, acc.y);
        acc.z = fmaf(nA, vA.z, acc.z); acc.w = fmaf(nA, vA.w, acc.w);
        acc.x = fmaf(nB, vB.x, acc.x); acc.y = fmaf(nB, vB.y, acc.y);
        acc.z = fmaf(nB, vB.z, acc.z); acc.w = fmaf(nB, vB.w, acc.w);
    }
    if (j < e) {
        int sA = g_esrc[j];
        float nA = g_enorm[j];
        float4 vA = Ab[(size_t)sA*32 + lane];
        acc.x = fmaf(nA, vA.x, acc.x); acc.y = fmaf(nA, vA.y, acc.y);
        acc.z = fmaf(nA, vA.z, acc.z); acc.w = fmaf(nA, vA.w, acc.w);
    }
    ((float4*)(H + ((size_t)b*NN + n)*FD))[lane] = acc;
}

// ---------------- per-feature sum/sumsq of relu(H) (read-only) ----------------
__global__ void k_relustats(int statoff) {
    int f = threadIdx.x;               // 128 threads = features
    long rb = (long)blockIdx.x * 64;
    float s = 0.f, s2 = 0.f;
    for (int i = 0; i < 64; i++) {
        long r = rb + i;
        if (r < MR) {
            float v = fmaxf(g_bufH[r*FD + f], 0.f);
            s += v; s2 += v*v;
        }
    }
    atomicAdd(&g_stats[statoff + f], s);
    atomicAdd(&g_stats[statoff + 128 + f], s2);
}

// ---------------- fold BN1 into W2: W2' = a1⊙W2, cw2 = c1@W2 ----------------
__global__ void k_fin1(const float* __restrict__ W2, const float* __restrict__ g1,
                       const float* __restrict__ be1) {
    __shared__ float a[FD], c[FD];
    int t = threadIdx.x;   // 128
    float inv = 1.0f / (float)MR;
    float mu  = g_stats[t] * inv;
    float var = g_stats[128 + t] * inv - mu*mu;
    float av  = g1[t] * rsqrtf(var + 1e-5f);
    a[t] = av; c[t] = be1[t] - mu*av;
    __syncthreads();
    float acc = 0.f;
    for (int f = 0; f < FD; f++) {
        float w = W2[f*FD + t];
        g_W2p[f*FD + t] = a[f]*w;
        acc = fmaf(c[f], w, acc);
    }
    g_cw2[t] = acc;
}

// ---------------- fold BN2 into Wc: Wc' = a2⊙Wc, bc' = bc + c2@Wc ----------------
__global__ void k_fin2(const float* __restrict__ Wc, const float* __restrict__ bc,
                       const float* __restrict__ g2, const float* __restrict__ be2) {
    __shared__ float a[FD], c[FD];
    int t = threadIdx.x;   // 128
    float inv = 1.0f / (float)MR;
    float mu  = g_stats[256 + t] * inv;
    float var = g_stats[384 + t] * inv - mu*mu;
    float av  = g2[t] * rsqrtf(var + 1e-5f);
    a[t] = av; c[t] = be2[t] - mu*av;
    __syncthreads();
    if (t < NOUT) {
        float acc = bc[t];
        for (int f = 0; f < FD; f++) {
            float w = Wc[f*NOUT + t];
            g_Wcp[f*NOUT + t] = a[f]*w;
            acc = fmaf(c[f], w, acc);
        }
        g_bcp[t] = acc;
    }
}

// ---------------- output head: out = relu(H) @ Wc' + bc' ----------------
__global__ void k_out(float* __restrict__ out) {
    __shared__ float Ws[FD*NOUT];
    __shared__ float Hs[8][FD];
    int t = threadIdx.x;   // 128
    #pragma unroll
    for (int i = 0; i < 16; i++) Ws[i*128 + t] = g_Wcp[i*128 + t];
    long rb = (long)blockIdx.x * 8;
    #pragma unroll
    for (int i = 0; i < 8; i++) {
        long r = rb + i;
        Hs[i][t] = (r < MR) ? fmaxf(g_bufH[r*FD + t], 0.f) : 0.f;
    }
    __syncthreads();
    int rl = t >> 4, c = t & 15;
    float acc = g_bcp[c];
    #pragma unroll 8
    for (int f = 0; f < FD; f++) acc = fmaf(Hs[rl][f], Ws[f*NOUT + c], acc);
    long r = rb + rl;
    if (r < MR) out[r*NOUT + c] = acc;
}

// ---------------- launcher ----------------
extern "C" void kernel_launch(void* const* d_in, const int* in_sizes, int n_in,
                              void* d_out, int out_size) {
    const float* x   = (const float*)d_in[0];
    const int*   ei  = (const int*)  d_in[1];
    const float* ewp = (const float*)d_in[2];
    const float* W1  = (const float*)d_in[3];
    const float* b1  = (const float*)d_in[4];
    const float* W2  = (const float*)d_in[5];
    const float* b2  = (const float*)d_in[6];
    const float* g1  = (const float*)d_in[7];
    const float* be1 = (const float*)d_in[8];
    const float* g2  = (const float*)d_in[9];
    const float* be2 = (const float*)d_in[10];
    const float* Wc  = (const float*)d_in[11];
    const float* bc  = (const float*)d_in[12];
    float* out = (float*)d_out;

    float *bufA, *bufH, *W2p, *cw2;
    cudaGetSymbolAddress((void**)&bufA, g_bufA);
    cudaGetSymbolAddress((void**)&bufH, g_bufH);
    cudaGetSymbolAddress((void**)&W2p,  g_W2p);
    cudaGetSymbolAddress((void**)&cw2,  g_cw2);

    const int gemmBlocks = (MR + 127) / 128;          // 782
    const dim3 aggGrid((NN + 7) / 8, NB);             // 6250 x 2

    // prep + CSR build (shared by both layers/batches)
    k_init<<<(NN + 255)/256, 256>>>();
    k_deghist<<<(NE + 255)/256, 256>>>(ei, ewp);
    k_dinv<<<(NN + 255)/256, 256>>>();
    k_scan1<<<SB, 1024>>>();
    k_scan2<<<1, 64>>>();
    k_scan3<<<SB, 1024>>>();
    k_fill<<<(NE + 255)/256, 256>>>(ei, ewp);

    // Layer 1
    k_gemm<<<gemmBlocks, 256>>>(x, W1, bufA, nullptr, 0);
    k_agg<<<aggGrid, 256>>>(bufA, bufH, b1);
    k_relustats<<<(MR + 63)/64, 128>>>(0);
    k_fin1<<<1, 128>>>(W2, g1, be1);

    // Layer 2 (ReLU applied in GEMM A-load; BN1 folded into W2p/cw2)
    k_gemm<<<gemmBlocks, 256>>>(bufH, W2p, bufA, cw2, 1);
    k_agg<<<aggGrid, 256>>>(bufA, bufH, b2);
    k_relustats<<<(MR + 63)/64, 128>>>(256);
    k_fin2<<<1, 128>>>(Wc, bc, g2, be2);

    // Head (ReLU applied in load; BN2 folded into Wcp/bcp)
    k_out<<<(MR + 7)/8, 128>>>(out);
}

// round 4
// speedup vs baseline: 2.0232x; 1.2988x over previous
#include <cuda_runtime.h>
#include <math.h>

#define NB 2
#define NN 50000
#define NE 640000
#define FD 128
#define NOUT 16
#define MR (NB*NN)   // 100000 rows
#define SB 49        // scan blocks (49*1024 >= NN)

// ---------------- device scratch (allocation-free) ----------------
__device__ __align__(256) float g_dinv[NN];
__device__ __align__(256) float g_deg[NN];
__device__ __align__(256) int   g_cnt[NN];
__device__ __align__(256) int   g_cur[NN];
__device__ __align__(256) int   g_rowptr[NN + 1];
__device__ __align__(256) int   g_bsum[SB];
__device__ __align__(256) int   g_boff[SB];
__device__ __align__(256) int   g_esrc[NE];     // src ids sorted by dst
__device__ __align__(256) float g_enorm[NE];    // norm sorted by dst
__device__ __align__(256) float g_bufA[(size_t)MR*FD];   // xw / xw2
__device__ __align__(256) float g_bufH[(size_t)MR*FD];   // aggregated h
__device__ __align__(256) float g_stats[512];            // sum/sumsq for 2 layers
__device__ __align__(256) float g_W2p[FD*FD];            // a1 ⊙ W2
__device__ __align__(256) float g_cw2[FD];               // c1 @ W2
__device__ __align__(256) float g_Wcp[FD*NOUT];          // a2 ⊙ Wc
__device__ __align__(256) float g_bcp[NOUT];             // bc + c2 @ Wc

// ---------------- prep: init, degree+histogram, dinv ----------------
__global__ void k_init() {
    int i = blockIdx.x*blockDim.x + threadIdx.x;
    if (i < NN) { g_deg[i] = 1.0f; g_cnt[i] = 0; }   // self-loop weight = 1
    if (i < 512) g_stats[i] = 0.0f;
}

__global__ void k_deghist(const int* __restrict__ ei, const float* __restrict__ ewp) {
    int e = blockIdx.x*blockDim.x + threadIdx.x;
    if (e >= NE) return;
    int dst = ei[NE + e];
    atomicAdd(&g_deg[dst], expf(ewp[e]));
    atomicAdd(&g_cnt[dst], 1);
}

__global__ void k_dinv() {
    int i = blockIdx.x*blockDim.x + threadIdx.x;
    if (i < NN) g_dinv[i] = rsqrtf(g_deg[i]);   // deg >= 1 always
}

// ---------------- parallel 3-phase exclusive scan over g_cnt ----------------
__global__ __launch_bounds__(1024) void k_scan1() {
    __shared__ int sh[1024];
    const int t = threadIdx.x;
    const int i = blockIdx.x * 1024 + t;
    int v = (i < NN) ? g_cnt[i] : 0;
    sh[t] = v;
    __syncthreads();
    #pragma unroll
    for (int off = 1; off < 1024; off <<= 1) {
        int x = (t >= off) ? sh[t - off] : 0;
        __syncthreads();
        sh[t] += x;
        __syncthreads();
    }
    if (i < NN) g_rowptr[i] = sh[t] - v;        // local exclusive prefix
    if (t == 1023) g_bsum[blockIdx.x] = sh[1023];
}

__global__ void k_scan2() {
    __shared__ int s[SB];
    int t = threadIdx.x;   // 64 threads
    if (t < SB) s[t] = g_bsum[t];
    __syncthreads();
    if (t == 0) {
        int run = 0;
        for (int i = 0; i < SB; i++) { int v = s[i]; s[i] = run; run += v; }
    }
    __syncthreads();
    if (t < SB) g_boff[t] = s[t];
}

__global__ __launch_bounds__(1024) void k_scan3() {
    const int i = blockIdx.x * 1024 + threadIdx.x;
    if (i < NN) {
        int v = g_rowptr[i] + g_boff[blockIdx.x];
        g_rowptr[i] = v;
        g_cur[i]    = v;
    }
    if (i == 0) g_rowptr[NN] = NE;
}

// ---------------- fill CSR buckets (src + norm, sorted by dst) ----------------
__global__ void k_fill(const int* __restrict__ ei, const float* __restrict__ ewp) {
    int e = blockIdx.x*blockDim.x + threadIdx.x;
    if (e >= NE) return;
    int src = ei[e], dst = ei[NE + e];
    int p = atomicAdd(&g_cur[dst], 1);
    g_esrc[p]  = src;
    g_enorm[p] = g_dinv[src] * expf(ewp[e]) * g_dinv[dst];
}

// ---------------- tf32 tensor-core GEMM ----------------
// C[MR,128] = reluA?(A)[MR,128] @ B[128,128] (+ biasRow)
__device__ __forceinline__ unsigned f2tf(float f) {
    unsigned r;
    asm("cvt.rna.tf32.f32 %0, %1;" : "=r"(r) : "f"(f));
    return r;
}

__global__ __launch_bounds__(256) void k_gemm(const float* __restrict__ A,
                                              const float* __restrict__ B,
                                              float* __restrict__ C,
                                              const float* __restrict__ biasRow,
                                              int reluA) {
    __shared__ unsigned As[128][12];   // [m][k], stride 12 -> conflict-free frags
    __shared__ unsigned Bs[8][136];    // [k][n], stride 136 -> conflict-free frags
    const int t    = threadIdx.x;
    const int warp = t >> 5;
    const int lane = t & 31;
    const int l4   = lane >> 2;        // 0..7
    const int lm4  = lane & 3;         // 0..3
    const int wr   = warp * 16;        // warp's row base in tile
    const long rowBase = (long)blockIdx.x * 128;

    // accumulators: 16 n-tiles x 4 regs, init with bias
    float c[16][4];
    #pragma unroll
    for (int nt = 0; nt < 16; nt++) {
        int col = nt*8 + 2*lm4;
        float bv0 = biasRow ? biasRow[col]     : 0.f;
        float bv1 = biasRow ? biasRow[col + 1] : 0.f;
        c[nt][0] = bv0; c[nt][1] = bv1;
        c[nt][2] = bv0; c[nt][3] = bv1;
    }

    // A load mapping: thread -> (row, 4 k's)
    const int arow = t >> 1;
    const int ak   = (t & 1) * 4;
    long arg = rowBase + arow; if (arg >= MR) arg = MR - 1;
    // B load mapping
    const int bk = t >> 5;             // 0..7
    const int bn = (t & 31) * 4;

    for (int kc = 0; kc < 16; kc++) {
        float4 av = *(const float4*)(A + arg*FD + kc*8 + ak);
        if (reluA) {
            av.x = fmaxf(av.x, 0.f); av.y = fmaxf(av.y, 0.f);
            av.z = fmaxf(av.z, 0.f); av.w = fmaxf(av.w, 0.f);
        }
        As[arow][ak+0] = f2tf(av.x); As[arow][ak+1] = f2tf(av.y);
        As[arow][ak+2] = f2tf(av.z); As[arow][ak+3] = f2tf(av.w);
        float4 bvv = *(const float4*)(B + (size_t)(kc*8 + bk)*FD + bn);
        Bs[bk][bn+0] = f2tf(bvv.x); Bs[bk][bn+1] = f2tf(bvv.y);
        Bs[bk][bn+2] = f2tf(bvv.z); Bs[bk][bn+3] = f2tf(bvv.w);
        __syncthreads();

        unsigned a0 = As[wr + l4    ][lm4    ];
        unsigned a1 = As[wr + l4 + 8][lm4    ];
        unsigned a2 = As[wr + l4    ][lm4 + 4];
        unsigned a3 = As[wr + l4 + 8][lm4 + 4];
        #pragma unroll
        for (int nt = 0; nt < 16; nt++) {
            unsigned b0 = Bs[lm4    ][nt*8 + l4];
            unsigned b1 = Bs[lm4 + 4][nt*8 + l4];
            asm volatile(
                "mma.sync.aligned.m16n8k8.row.col.f32.tf32.tf32.f32 "
                "{%0,%1,%2,%3}, {%4,%5,%6,%7}, {%8,%9}, {%0,%1,%2,%3};"
                : "+f"(c[nt][0]), "+f"(c[nt][1]), "+f"(c[nt][2]), "+f"(c[nt][3])
                : "r"(a0), "r"(a1), "r"(a2), "r"(a3), "r"(b0), "r"(b1));
        }
        __syncthreads();
    }

    long crow0 = rowBase + wr + l4;
    long crow1 = crow0 + 8;
    #pragma unroll
    for (int nt = 0; nt < 16; nt++) {
        int col = nt*8 + 2*lm4;
        if (crow0 < MR) *(float2*)(C + crow0*FD + col) = make_float2(c[nt][0], c[nt][1]);
        if (crow1 < MR) *(float2*)(C + crow1*FD + col) = make_float2(c[nt][2], c[nt][3]);
    }
}

// ---------------- CSR aggregation: one warp per node, single write ----------------
// H[b,n] = dinv[n]^2 * A[b,n] + bias + sum_{edges e: dst=n} norm[e] * A[b,src[e]]
__global__ __launch_bounds__(256) void k_agg(const float* __restrict__ A,
                                             float* __restrict__ H,
                                             const float* __restrict__ bias) {
    int warp = threadIdx.x >> 5;
    int lane = threadIdx.x & 31;
    int n = blockIdx.x * 8 + warp;
    if (n >= NN) return;
    int b = blockIdx.y;
    const float4* Ab = (const float4*)(A + (size_t)b*NN*FD);

    float d = g_dinv[n];
    float sn = d * d;
    float4 v  = Ab[(size_t)n*32 + lane];
    float4 bv = ((const float4*)bias)[lane];
    float4 acc;
    acc.x = fmaf(sn, v.x, bv.x);
    acc.y = fmaf(sn, v.y, bv.y);
    acc.z = fmaf(sn, v.z, bv.z);
    acc.w = fmaf(sn, v.w, bv.w);

    int j = g_rowptr[n];
    const int e = g_rowptr[n + 1];
    for (; j + 1 < e; j += 2) {
        int sA = g_esrc[j],   sB2 = g_esrc[j+1];
        float nA = g_enorm[j], nB = g_enorm[j+1];
        float4 vA = Ab[(size_t)sA*32 + lane];
        float4 vB = Ab[(size_t)sB2*32 + lane];
        acc.x = fmaf(nA, vA.x, acc.x); acc.y = fmaf(nA, vA.y, acc.y);
        acc.z = fmaf(nA, vA.z, acc.z); acc.w = fmaf(nA, vA.w, acc.w);
        acc.x = fmaf(nB, vB.x, acc.x); acc.y = fmaf(nB, vB.y, acc.y);
        acc.z = fmaf(nB, vB.z, acc.z); acc.w = fmaf(nB, vB.w, acc.w);
    }
    if (j < e) {
        int sA = g_esrc[j];
        float nA = g_enorm[j];
        float4 vA = Ab[(size_t)sA*32 + lane];
        acc.x = fmaf(nA, vA.x, acc.x); acc.y = fmaf(nA, vA.y, acc.y);
        acc.z = fmaf(nA, vA.z, acc.z); acc.w = fmaf(nA, vA.w, acc.w);
    }
    ((float4*)(H + ((size_t)b*NN + n)*FD))[lane] = acc;
}

// ---------------- per-feature sum/sumsq of relu(H) (read-only) ----------------
__global__ void k_relustats(int statoff) {
    int f = threadIdx.x;               // 128 threads = features
    long rb = (long)blockIdx.x * 64;
    float s = 0.f, s2 = 0.f;
    for (int i = 0; i < 64; i++) {
        long r = rb + i;
        if (r < MR) {
            float v = fmaxf(g_bufH[r*FD + f], 0.f);
            s += v; s2 += v*v;
        }
    }
    atomicAdd(&g_stats[statoff + f], s);
    atomicAdd(&g_stats[statoff + 128 + f], s2);
}

// ---------------- fold BN1 into W2: W2' = a1⊙W2, cw2 = c1@W2 ----------------
__global__ void k_fin1(const float* __restrict__ W2, const float* __restrict__ g1,
                       const float* __restrict__ be1) {
    __shared__ float a[FD], c[FD];
    int t = threadIdx.x;   // 128
    float inv = 1.0f / (float)MR;
    float mu  = g_stats[t] * inv;
    float var = g_stats[128 + t] * inv - mu*mu;
    float av  = g1[t] * rsqrtf(var + 1e-5f);
    a[t] = av; c[t] = be1[t] - mu*av;
    __syncthreads();
    float acc = 0.f;
    for (int f = 0; f < FD; f++) {
        float w = W2[f*FD + t];
        g_W2p[f*FD + t] = a[f]*w;
        acc = fmaf(c[f], w, acc);
    }
    g_cw2[t] = acc;
}

// ---------------- fold BN2 into Wc: Wc' = a2⊙Wc, bc' = bc + c2@Wc ----------------
__global__ void k_fin2(const float* __restrict__ Wc, const float* __restrict__ bc,
                       const float* __restrict__ g2, const float* __restrict__ be2) {
    __shared__ float a[FD], c[FD];
    int t = threadIdx.x;   // 128
    float inv = 1.0f / (float)MR;
    float mu  = g_stats[256 + t] * inv;
    float var = g_stats[384 + t] * inv - mu*mu;
    float av  = g2[t] * rsqrtf(var + 1e-5f);
    a[t] = av; c[t] = be2[t] - mu*av;
    __syncthreads();
    if (t < NOUT) {
        float acc = bc[t];
        for (int f = 0; f < FD; f++) {
            float w = Wc[f*NOUT + t];
            g_Wcp[f*NOUT + t] = a[f]*w;
            acc = fmaf(c[f], w, acc);
        }
        g_bcp[t] = acc;
    }
}

// ---------------- output head: out = relu(H) @ Wc' + bc' ----------------
__global__ void k_out(float* __restrict__ out) {
    __shared__ float Ws[FD*NOUT];
    __shared__ float Hs[8][FD];
    int t = threadIdx.x;   // 128
    #pragma unroll
    for (int i = 0; i < 16; i++) Ws[i*128 + t] = g_Wcp[i*128 + t];
    long rb = (long)blockIdx.x * 8;
    #pragma unroll
    for (int i = 0; i < 8; i++) {
        long r = rb + i;
        Hs[i][t] = (r < MR) ? fmaxf(g_bufH[r*FD + t], 0.f) : 0.f;
    }
    __syncthreads();
    int rl = t >> 4, c = t & 15;
    float acc = g_bcp[c];
    #pragma unroll 8
    for (int f = 0; f < FD; f++) acc = fmaf(Hs[rl][f], Ws[f*NOUT + c], acc);
    long r = rb + rl;
    if (r < MR) out[r*NOUT + c] = acc;
}

// ---------------- launcher ----------------
extern "C" void kernel_launch(void* const* d_in, const int* in_sizes, int n_in,
                              void* d_out, int out_size) {
    const float* x   = (const float*)d_in[0];
    const int*   ei  = (const int*)  d_in[1];
    const float* ewp = (const float*)d_in[2];
    const float* W1  = (const float*)d_in[3];
    const float* b1  = (const float*)d_in[4];
    const float* W2  = (const float*)d_in[5];
    const float* b2  = (const float*)d_in[6];
    const float* g1  = (const float*)d_in[7];
    const float* be1 = (const float*)d_in[8];
    const float* g2  = (const float*)d_in[9];
    const float* be2 = (const float*)d_in[10];
    const float* Wc  = (const float*)d_in[11];
    const float* bc  = (const float*)d_in[12];
    float* out = (float*)d_out;

    float *bufA, *bufH, *W2p, *cw2;
    cudaGetSymbolAddress((void**)&bufA, g_bufA);
    cudaGetSymbolAddress((void**)&bufH, g_bufH);
    cudaGetSymbolAddress((void**)&W2p,  g_W2p);
    cudaGetSymbolAddress((void**)&cw2,  g_cw2);

    const int gemmBlocks = (MR + 127) / 128;          // 782
    const dim3 aggGrid((NN + 7) / 8, NB);             // 6250 x 2

    // prep + CSR build (shared by both layers/batches)
    k_init<<<(NN + 255)/256, 256>>>();
    k_deghist<<<(NE + 255)/256, 256>>>(ei, ewp);
    k_dinv<<<(NN + 255)/256, 256>>>();
    k_scan1<<<SB, 1024>>>();
    k_scan2<<<1, 64>>>();
    k_scan3<<<SB, 1024>>>();
    k_fill<<<(NE + 255)/256, 256>>>(ei, ewp);

    // Layer 1
    k_gemm<<<gemmBlocks, 256>>>(x, W1, bufA, nullptr, 0);
    k_agg<<<aggGrid, 256>>>(bufA, bufH, b1);
    k_relustats<<<(MR + 63)/64, 128>>>(0);
    k_fin1<<<1, 128>>>(W2, g1, be1);

    // Layer 2 (ReLU applied in GEMM A-load; BN1 folded into W2p/cw2)
    k_gemm<<<gemmBlocks, 256>>>(bufH, W2p, bufA, cw2, 1);
    k_agg<<<aggGrid, 256>>>(bufA, bufH, b2);
    k_relustats<<<(MR + 63)/64, 128>>>(256);
    k_fin2<<<1, 128>>>(Wc, bc, g2, be2);

    // Head (ReLU applied in load; BN2 folded into Wcp/bcp)
    k_out<<<(MR + 7)/8, 128>>>(out);
}